// round 4
// baseline (speedup 1.0000x reference)
#include <cuda_runtime.h>

#define BB 32
#define SS 8192
#define DD 256
#define KSEL 1638          // max(1, int(8192*0.2))
#define NCHUNK 32
#define ROWS_PER_CHUNK 256 // SS / NCHUNK
#define ROWS_PER_WARP 32
#define ECHUNK 8           // kB blocks per batch

// Scratch (no allocations allowed)
__device__ float g_w[BB * SS];                 // exp(tanh(x.W + b))
__device__ float g_Ppart[NCHUNK * BB * DD];    // per-chunk partial sum x*w (all rows)
__device__ float g_Epart[ECHUNK * BB * DD];    // per-chunk partial sum x*w (top-k rows)
__device__ float g_Psum[BB * DD];              // chunk-reduced P (computed in kA tail)
__device__ float g_invZ[BB];
__device__ int   g_idx[BB * SS];               // compacted accepted row indices
__device__ int   g_cntE[BB];                   // accepted count per batch
__device__ int   g_cnt1[BB];                   // arrival counters (self-resetting)
__device__ int   g_cnt2[BB];

// Branch-free w = exp(tanh(z)):  tanh(z) = 1 - 2/(e^{2z}+1)
__device__ __forceinline__ float exp_tanh(float z)
{
    const float ez = __expf(z + z);
    const float t  = 1.0f - __fdividef(2.0f, ez + 1.0f);
    return __expf(t);
}

// ---------------------------------------------------------------------------
// kA: k1 (dot, activation, P partials) + per-batch last-block tail doing k2
// (Z, exact threshold via bitwise binary search, emphasized_a, Psum, and a
// deterministic ordered compaction of accepted row indices).
// ---------------------------------------------------------------------------
__global__ __launch_bounds__(256, 2) void kA_kernel(const float* __restrict__ x,
                                                    const float* __restrict__ W,
                                                    const float* __restrict__ bias,
                                                    float* __restrict__ out_a)
{
    const int blk   = blockIdx.x;
    const int b     = blk / NCHUNK;
    const int chunk = blk % NCHUNK;
    const int warp  = threadIdx.x >> 5;
    const int lane  = threadIdx.x & 31;
    const int rowlocal = lane >> 3;   // 0..3
    const int e        = lane & 7;    // 0..7

    const float4* Wf4 = (const float4*)W;
    float4 wreg4[8];
#pragma unroll
    for (int j = 0; j < 8; j++) wreg4[j] = Wf4[j * 8 + e];
    const float bv = bias[0];

    float4 acc[8];
#pragma unroll
    for (int j = 0; j < 8; j++) acc[j] = make_float4(0.f, 0.f, 0.f, 0.f);

    const int s0 = chunk * ROWS_PER_CHUNK + warp * ROWS_PER_WARP;
    const float4* xb = (const float4*)(x + (size_t)b * SS * DD);

    for (int gi = 0; gi < 8; gi++) {
        const int srow = s0 + gi * 4 + rowlocal;
        const float4* xr = xb + (size_t)srow * (DD / 4);

        float4 v[8];
#pragma unroll
        for (int j = 0; j < 8; j++) v[j] = xr[j * 8 + e];   // d = j*32 + e*4

        float dp = 0.f;
#pragma unroll
        for (int j = 0; j < 8; j++)
            dp += v[j].x * wreg4[j].x + v[j].y * wreg4[j].y
                + v[j].z * wreg4[j].z + v[j].w * wreg4[j].w;

        dp += __shfl_xor_sync(0xffffffffu, dp, 1);
        dp += __shfl_xor_sync(0xffffffffu, dp, 2);
        dp += __shfl_xor_sync(0xffffffffu, dp, 4);

        const float wv = exp_tanh(dp + bv);
        if (e == 0) g_w[b * SS + srow] = wv;

#pragma unroll
        for (int j = 0; j < 8; j++) {
            acc[j].x += v[j].x * wv; acc[j].y += v[j].y * wv;
            acc[j].z += v[j].z * wv; acc[j].w += v[j].w * wv;
        }
    }

#pragma unroll
    for (int j = 0; j < 8; j++) {
        acc[j].x += __shfl_xor_sync(0xffffffffu, acc[j].x, 8);
        acc[j].y += __shfl_xor_sync(0xffffffffu, acc[j].y, 8);
        acc[j].z += __shfl_xor_sync(0xffffffffu, acc[j].z, 8);
        acc[j].w += __shfl_xor_sync(0xffffffffu, acc[j].w, 8);
        acc[j].x += __shfl_xor_sync(0xffffffffu, acc[j].x, 16);
        acc[j].y += __shfl_xor_sync(0xffffffffu, acc[j].y, 16);
        acc[j].z += __shfl_xor_sync(0xffffffffu, acc[j].z, 16);
        acc[j].w += __shfl_xor_sync(0xffffffffu, acc[j].w, 16);
    }

    __shared__ float4 sacc[8][64];   // [warp][d/4]
    if (lane < 8) {
#pragma unroll
        for (int j = 0; j < 8; j++) sacc[warp][j * 8 + e] = acc[j];
    }
    __syncthreads();

    {
        float tot = 0.f;
        const float* sflat = (const float*)sacc;
#pragma unroll
        for (int wp = 0; wp < 8; wp++) tot += sflat[wp * DD + threadIdx.x];
        g_Ppart[((size_t)chunk * BB + b) * DD + threadIdx.x] = tot;
    }

    // ---- last-block-per-batch gate ----
    __threadfence();
    __shared__ int slast;
    if (threadIdx.x == 0) {
        const int old = atomicAdd(&g_cnt1[b], 1);
        slast = (old == NCHUNK - 1);
        if (slast) g_cnt1[b] = 0;           // reset for next graph replay
    }
    __syncthreads();
    if (!slast) return;

    // =================== k2 tail for batch b ===================
    const int t = threadIdx.x;

    float wreg[32];
#pragma unroll
    for (int j = 0; j < 32; j++) wreg[j] = g_w[b * SS + j * 256 + t];

    __shared__ float sredf[8];
    __shared__ float sZ;
    __shared__ int   stot[32];
    if (t < 32) stot[t] = 0;

    // Z = sum(w)
    float z = 0.f;
#pragma unroll
    for (int j = 0; j < 32; j++) z += wreg[j];
#pragma unroll
    for (int off = 16; off; off >>= 1) z += __shfl_xor_sync(0xffffffffu, z, off);
    if (lane == 0) sredf[warp] = z;
    __syncthreads();
    if (t == 0) {
        float zz = 0.f;
        for (int i = 0; i < 8; i++) zz += sredf[i];
        sZ = zz;
    }

    // P chunk-reduction folded in (overlaps the barrier)
    {
        float p = 0.f;
#pragma unroll
        for (int c = 0; c < NCHUNK; c++)
            p += g_Ppart[((size_t)c * BB + b) * DD + t];
        g_Psum[b * DD + t] = p;
    }
    __syncthreads();
    const float invZ = 1.f / sZ;

    // exact KSEL-th largest via binary search on float bit patterns
    unsigned lo = 0x3E800000u;  // 0.25f
    unsigned hi = 0x40800000u;  // 4.0f
    int it = 0;
    while (hi - lo > 1u) {
        const unsigned mid = lo + ((hi - lo) >> 1);
        const float fm = __uint_as_float(mid);
        int c = 0;
#pragma unroll
        for (int j = 0; j < 32; j++) c += (wreg[j] >= fm);
        c = __reduce_add_sync(0xffffffffu, c);
        if (lane == 0) atomicAdd(&stot[it], c);
        __syncthreads();
        if (stot[it] >= KSEL) lo = mid; else hi = mid;
        it++;
    }
    const float thr = __uint_as_float(lo);
    if (t == 0) g_invZ[b] = invZ;

    // emphasized_a + accept mask
    unsigned accmask = 0u;
    int cnt = 0;
#pragma unroll
    for (int j = 0; j < 32; j++) {
        const float wv = wreg[j];
        const bool a = (wv >= thr);
        accmask |= (a ? 1u : 0u) << j;
        cnt += a ? 1 : 0;
        out_a[b * SS + j * 256 + t] = wv * invZ * (a ? 1.5f : 1.0f);
    }

    // deterministic ordered compaction of accepted indices
    int v = cnt;
#pragma unroll
    for (int off = 1; off < 32; off <<= 1) {
        const int n = __shfl_up_sync(0xffffffffu, v, off);
        if (lane >= off) v += n;
    }
    __shared__ int swsum[8];
    __shared__ int swbase[8];
    if (lane == 31) swsum[warp] = v;
    __syncthreads();
    if (t == 0) {
        int s = 0;
        for (int i = 0; i < 8; i++) { swbase[i] = s; s += swsum[i]; }
        g_cntE[b] = s;
    }
    __syncthreads();
    int base = swbase[warp] + v - cnt;   // exclusive prefix for this thread
    int* dst = g_idx + b * SS;
#pragma unroll
    for (int j = 0; j < 32; j++) {
        if ((accmask >> j) & 1u) dst[base++] = j * 256 + t;
    }
}

// ---------------------------------------------------------------------------
// kB: dense gather over compacted index list (unconditional loads, 2-row
// unroll for MLP) + per-batch last-block tail doing the final combine.
// Grid: BB*ECHUNK blocks x 256 threads. Global warp g = chunk*8+warp handles
// slots g, g+64, g+128, ...
// ---------------------------------------------------------------------------
__global__ __launch_bounds__(256) void kB_kernel(const float* __restrict__ x,
                                                 float* __restrict__ out_sum)
{
    const int b     = blockIdx.x >> 3;
    const int chunk = blockIdx.x & 7;
    const int warp  = threadIdx.x >> 5;
    const int lane  = threadIdx.x & 31;
    const int g     = chunk * 8 + warp;   // 0..63

    const int cnt = g_cntE[b];
    const int*   idx  = g_idx + b * SS;
    const float* wrow = g_w + b * SS;
    const float4* xb  = (const float4*)(x + (size_t)b * SS * DD);

    float acc[8];
#pragma unroll
    for (int j = 0; j < 8; j++) acc[j] = 0.f;

    int s = g;
    for (; s + 64 < cnt; s += 128) {
        const int r0 = idx[s];
        const int r1 = idx[s + 64];
        const float w0 = wrow[r0];
        const float w1 = wrow[r1];
        const float4* x0 = xb + (size_t)r0 * (DD / 4);
        const float4* x1 = xb + (size_t)r1 * (DD / 4);
        float4 a0 = x0[lane], a1 = x0[32 + lane];
        float4 b0 = x1[lane], b1 = x1[32 + lane];
        acc[0] += a0.x * w0 + b0.x * w1; acc[1] += a0.y * w0 + b0.y * w1;
        acc[2] += a0.z * w0 + b0.z * w1; acc[3] += a0.w * w0 + b0.w * w1;
        acc[4] += a1.x * w0 + b1.x * w1; acc[5] += a1.y * w0 + b1.y * w1;
        acc[6] += a1.z * w0 + b1.z * w1; acc[7] += a1.w * w0 + b1.w * w1;
    }
    for (; s < cnt; s += 64) {
        const int r0 = idx[s];
        const float w0 = wrow[r0];
        const float4* x0 = xb + (size_t)r0 * (DD / 4);
        float4 a0 = x0[lane], a1 = x0[32 + lane];
        acc[0] += a0.x * w0; acc[1] += a0.y * w0;
        acc[2] += a0.z * w0; acc[3] += a0.w * w0;
        acc[4] += a1.x * w0; acc[5] += a1.y * w0;
        acc[6] += a1.z * w0; acc[7] += a1.w * w0;
    }

    __shared__ float sacc[8][DD];
#pragma unroll
    for (int j = 0; j < 4; j++) {
        sacc[warp][lane * 4 + j]       = acc[j];
        sacc[warp][128 + lane * 4 + j] = acc[4 + j];
    }
    __syncthreads();
    {
        float tot = 0.f;
#pragma unroll
        for (int wp = 0; wp < 8; wp++) tot += sacc[wp][threadIdx.x];
        g_Epart[((size_t)chunk * BB + b) * DD + threadIdx.x] = tot;
    }

    // ---- last-block-per-batch gate ----
    __threadfence();
    __shared__ int slast;
    if (threadIdx.x == 0) {
        const int old = atomicAdd(&g_cnt2[b], 1);
        slast = (old == ECHUNK - 1);
        if (slast) g_cnt2[b] = 0;
    }
    __syncthreads();
    if (!slast) return;

    // =================== k4 tail for batch b ===================
    const int t = threadIdx.x;
    float esum = 0.f;
#pragma unroll
    for (int c = 0; c < ECHUNK; c++)
        esum += g_Epart[((size_t)c * BB + b) * DD + t];
    out_sum[b * DD + t] = g_invZ[b] * (g_Psum[b * DD + t] + 0.5f * esum);
}

// ---------------------------------------------------------------------------
extern "C" void kernel_launch(void* const* d_in, const int* in_sizes, int n_in,
                              void* d_out, int out_size)
{
    const float* x    = (const float*)d_in[0];
    const float* W    = (const float*)d_in[1];
    const float* bias = (const float*)d_in[2];

    float* out      = (float*)d_out;
    float* out_sum  = out;              // [BB, DD]
    float* out_a    = out + BB * DD;    // [BB, SS]

    kA_kernel<<<BB * NCHUNK, 256>>>(x, W, bias, out_a);
    kB_kernel<<<BB * ECHUNK, 256>>>(x, out_sum);
}

// round 5
// speedup vs baseline: 1.0105x; 1.0105x over previous
#include <cuda_runtime.h>

#define BB 32
#define SS 8192
#define DD 256
#define KSEL 1638          // max(1, int(8192*0.2))
#define NCHUNK 32
#define ROWS_PER_CHUNK 256 // SS / NCHUNK
#define ROWS_PER_WARP 32
#define ECHUNK 8           // kB blocks per batch

// Scratch (no allocations allowed)
__device__ float g_w[BB * SS];                 // exp(tanh(x.W + b))
__device__ float g_Ppart[NCHUNK * BB * DD];    // per-chunk partial sum x*w (all rows)
__device__ float g_Epart[ECHUNK * BB * DD];    // per-chunk partial sum x*w (top-k rows)
__device__ float g_Psum[BB * DD];              // chunk-reduced P (computed in kA tail)
__device__ float g_invZ[BB];
__device__ int   g_idx[BB * SS];               // compacted accepted row indices
__device__ int   g_cntE[BB];                   // accepted count per batch
__device__ int   g_cnt1[BB];                   // arrival counters (self-resetting)
__device__ int   g_cnt2[BB];

// Branch-free w = exp(tanh(z)):  tanh(z) = 1 - 2/(e^{2z}+1)
__device__ __forceinline__ float exp_tanh(float z)
{
    const float ez = __expf(z + z);
    const float t  = 1.0f - __fdividef(2.0f, ez + 1.0f);
    return __expf(t);
}

// ---------------------------------------------------------------------------
// kA: k1 (dot, activation, P partials) + per-batch last-block tail doing k2
// (Z, exact threshold via bitwise binary search, emphasized_a, Psum, and a
// deterministic ordered compaction of accepted row indices).
// ---------------------------------------------------------------------------
__global__ __launch_bounds__(256, 2) void kA_kernel(const float* __restrict__ x,
                                                    const float* __restrict__ W,
                                                    const float* __restrict__ bias,
                                                    float* __restrict__ out_a)
{
    const int blk   = blockIdx.x;
    const int b     = blk / NCHUNK;
    const int chunk = blk % NCHUNK;
    const int warp  = threadIdx.x >> 5;
    const int lane  = threadIdx.x & 31;
    const int rowlocal = lane >> 3;   // 0..3
    const int e        = lane & 7;    // 0..7

    const float4* Wf4 = (const float4*)W;
    float4 wreg4[8];
#pragma unroll
    for (int j = 0; j < 8; j++) wreg4[j] = Wf4[j * 8 + e];
    const float bv = bias[0];

    float4 acc[8];
#pragma unroll
    for (int j = 0; j < 8; j++) acc[j] = make_float4(0.f, 0.f, 0.f, 0.f);

    const int s0 = chunk * ROWS_PER_CHUNK + warp * ROWS_PER_WARP;
    const float4* xb = (const float4*)(x + (size_t)b * SS * DD);

    for (int gi = 0; gi < 8; gi++) {
        const int srow = s0 + gi * 4 + rowlocal;
        const float4* xr = xb + (size_t)srow * (DD / 4);

        float4 v[8];
#pragma unroll
        for (int j = 0; j < 8; j++) v[j] = xr[j * 8 + e];   // d = j*32 + e*4

        float dp = 0.f;
#pragma unroll
        for (int j = 0; j < 8; j++)
            dp += v[j].x * wreg4[j].x + v[j].y * wreg4[j].y
                + v[j].z * wreg4[j].z + v[j].w * wreg4[j].w;

        dp += __shfl_xor_sync(0xffffffffu, dp, 1);
        dp += __shfl_xor_sync(0xffffffffu, dp, 2);
        dp += __shfl_xor_sync(0xffffffffu, dp, 4);

        const float wv = exp_tanh(dp + bv);
        if (e == 0) g_w[b * SS + srow] = wv;

#pragma unroll
        for (int j = 0; j < 8; j++) {
            acc[j].x += v[j].x * wv; acc[j].y += v[j].y * wv;
            acc[j].z += v[j].z * wv; acc[j].w += v[j].w * wv;
        }
    }

#pragma unroll
    for (int j = 0; j < 8; j++) {
        acc[j].x += __shfl_xor_sync(0xffffffffu, acc[j].x, 8);
        acc[j].y += __shfl_xor_sync(0xffffffffu, acc[j].y, 8);
        acc[j].z += __shfl_xor_sync(0xffffffffu, acc[j].z, 8);
        acc[j].w += __shfl_xor_sync(0xffffffffu, acc[j].w, 8);
        acc[j].x += __shfl_xor_sync(0xffffffffu, acc[j].x, 16);
        acc[j].y += __shfl_xor_sync(0xffffffffu, acc[j].y, 16);
        acc[j].z += __shfl_xor_sync(0xffffffffu, acc[j].z, 16);
        acc[j].w += __shfl_xor_sync(0xffffffffu, acc[j].w, 16);
    }

    __shared__ float4 sacc[8][64];   // [warp][d/4]
    if (lane < 8) {
#pragma unroll
        for (int j = 0; j < 8; j++) sacc[warp][j * 8 + e] = acc[j];
    }
    __syncthreads();

    {
        float tot = 0.f;
        const float* sflat = (const float*)sacc;
#pragma unroll
        for (int wp = 0; wp < 8; wp++) tot += sflat[wp * DD + threadIdx.x];
        g_Ppart[((size_t)chunk * BB + b) * DD + threadIdx.x] = tot;
    }

    // ---- last-block-per-batch gate ----
    __threadfence();
    __shared__ int slast;
    if (threadIdx.x == 0) {
        const int old = atomicAdd(&g_cnt1[b], 1);
        slast = (old == NCHUNK - 1);
        if (slast) g_cnt1[b] = 0;           // reset for next graph replay
    }
    __syncthreads();
    if (!slast) return;

    // =================== k2 tail for batch b ===================
    const int t = threadIdx.x;

    float wreg[32];
#pragma unroll
    for (int j = 0; j < 32; j++) wreg[j] = g_w[b * SS + j * 256 + t];

    __shared__ float sredf[8];
    __shared__ float sZ;
    __shared__ int   stot[32];
    if (t < 32) stot[t] = 0;

    // Z = sum(w)
    float z = 0.f;
#pragma unroll
    for (int j = 0; j < 32; j++) z += wreg[j];
#pragma unroll
    for (int off = 16; off; off >>= 1) z += __shfl_xor_sync(0xffffffffu, z, off);
    if (lane == 0) sredf[warp] = z;
    __syncthreads();
    if (t == 0) {
        float zz = 0.f;
        for (int i = 0; i < 8; i++) zz += sredf[i];
        sZ = zz;
    }

    // P chunk-reduction folded in (overlaps the barrier)
    {
        float p = 0.f;
#pragma unroll
        for (int c = 0; c < NCHUNK; c++)
            p += g_Ppart[((size_t)c * BB + b) * DD + t];
        g_Psum[b * DD + t] = p;
    }
    __syncthreads();
    const float invZ = 1.f / sZ;

    // exact KSEL-th largest via binary search on float bit patterns
    unsigned lo = 0x3E800000u;  // 0.25f
    unsigned hi = 0x40800000u;  // 4.0f
    int it = 0;
    while (hi - lo > 1u) {
        const unsigned mid = lo + ((hi - lo) >> 1);
        const float fm = __uint_as_float(mid);
        int c = 0;
#pragma unroll
        for (int j = 0; j < 32; j++) c += (wreg[j] >= fm);
        c = __reduce_add_sync(0xffffffffu, c);
        if (lane == 0) atomicAdd(&stot[it], c);
        __syncthreads();
        if (stot[it] >= KSEL) lo = mid; else hi = mid;
        it++;
    }
    const float thr = __uint_as_float(lo);
    if (t == 0) g_invZ[b] = invZ;

    // emphasized_a + accept mask
    unsigned accmask = 0u;
    int cnt = 0;
#pragma unroll
    for (int j = 0; j < 32; j++) {
        const float wv = wreg[j];
        const bool a = (wv >= thr);
        accmask |= (a ? 1u : 0u) << j;
        cnt += a ? 1 : 0;
        out_a[b * SS + j * 256 + t] = wv * invZ * (a ? 1.5f : 1.0f);
    }

    // deterministic ordered compaction of accepted indices
    int v = cnt;
#pragma unroll
    for (int off = 1; off < 32; off <<= 1) {
        const int n = __shfl_up_sync(0xffffffffu, v, off);
        if (lane >= off) v += n;
    }
    __shared__ int swsum[8];
    __shared__ int swbase[8];
    if (lane == 31) swsum[warp] = v;
    __syncthreads();
    if (t == 0) {
        int s = 0;
        for (int i = 0; i < 8; i++) { swbase[i] = s; s += swsum[i]; }
        g_cntE[b] = s;
    }
    __syncthreads();
    int base = swbase[warp] + v - cnt;   // exclusive prefix for this thread
    int* dst = g_idx + b * SS;
#pragma unroll
    for (int j = 0; j < 32; j++) {
        if ((accmask >> j) & 1u) dst[base++] = j * 256 + t;
    }
}

// ---------------------------------------------------------------------------
// kB: dense gather over compacted index list (unconditional loads, 2-row
// unroll for MLP) + per-batch last-block tail doing the final combine.
// Grid: BB*ECHUNK blocks x 256 threads. Global warp g = chunk*8+warp handles
// slots g, g+64, g+128, ...
// ---------------------------------------------------------------------------
__global__ __launch_bounds__(256) void kB_kernel(const float* __restrict__ x,
                                                 float* __restrict__ out_sum)
{
    const int b     = blockIdx.x >> 3;
    const int chunk = blockIdx.x & 7;
    const int warp  = threadIdx.x >> 5;
    const int lane  = threadIdx.x & 31;
    const int g     = chunk * 8 + warp;   // 0..63

    const int cnt = g_cntE[b];
    const int*   idx  = g_idx + b * SS;
    const float* wrow = g_w + b * SS;
    const float4* xb  = (const float4*)(x + (size_t)b * SS * DD);

    float acc[8];
#pragma unroll
    for (int j = 0; j < 8; j++) acc[j] = 0.f;

    int s = g;
    for (; s + 64 < cnt; s += 128) {
        const int r0 = idx[s];
        const int r1 = idx[s + 64];
        const float w0 = wrow[r0];
        const float w1 = wrow[r1];
        const float4* x0 = xb + (size_t)r0 * (DD / 4);
        const float4* x1 = xb + (size_t)r1 * (DD / 4);
        float4 a0 = x0[lane], a1 = x0[32 + lane];
        float4 b0 = x1[lane], b1 = x1[32 + lane];
        acc[0] += a0.x * w0 + b0.x * w1; acc[1] += a0.y * w0 + b0.y * w1;
        acc[2] += a0.z * w0 + b0.z * w1; acc[3] += a0.w * w0 + b0.w * w1;
        acc[4] += a1.x * w0 + b1.x * w1; acc[5] += a1.y * w0 + b1.y * w1;
        acc[6] += a1.z * w0 + b1.z * w1; acc[7] += a1.w * w0 + b1.w * w1;
    }
    for (; s < cnt; s += 64) {
        const int r0 = idx[s];
        const float w0 = wrow[r0];
        const float4* x0 = xb + (size_t)r0 * (DD / 4);
        float4 a0 = x0[lane], a1 = x0[32 + lane];
        acc[0] += a0.x * w0; acc[1] += a0.y * w0;
        acc[2] += a0.z * w0; acc[3] += a0.w * w0;
        acc[4] += a1.x * w0; acc[5] += a1.y * w0;
        acc[6] += a1.z * w0; acc[7] += a1.w * w0;
    }

    __shared__ float sacc[8][DD];
#pragma unroll
    for (int j = 0; j < 4; j++) {
        sacc[warp][lane * 4 + j]       = acc[j];
        sacc[warp][128 + lane * 4 + j] = acc[4 + j];
    }
    __syncthreads();
    {
        float tot = 0.f;
#pragma unroll
        for (int wp = 0; wp < 8; wp++) tot += sacc[wp][threadIdx.x];
        g_Epart[((size_t)chunk * BB + b) * DD + threadIdx.x] = tot;
    }

    // ---- last-block-per-batch gate ----
    __threadfence();
    __shared__ int slast;
    if (threadIdx.x == 0) {
        const int old = atomicAdd(&g_cnt2[b], 1);
        slast = (old == ECHUNK - 1);
        if (slast) g_cnt2[b] = 0;
    }
    __syncthreads();
    if (!slast) return;

    // =================== k4 tail for batch b ===================
    const int t = threadIdx.x;
    float esum = 0.f;
#pragma unroll
    for (int c = 0; c < ECHUNK; c++)
        esum += g_Epart[((size_t)c * BB + b) * DD + t];
    out_sum[b * DD + t] = g_invZ[b] * (g_Psum[b * DD + t] + 0.5f * esum);
}

// ---------------------------------------------------------------------------
extern "C" void kernel_launch(void* const* d_in, const int* in_sizes, int n_in,
                              void* d_out, int out_size)
{
    const float* x    = (const float*)d_in[0];
    const float* W    = (const float*)d_in[1];
    const float* bias = (const float*)d_in[2];

    float* out      = (float*)d_out;
    float* out_sum  = out;              // [BB, DD]
    float* out_a    = out + BB * DD;    // [BB, SS]

    kA_kernel<<<BB * NCHUNK, 256>>>(x, W, bias, out_a);
    kB_kernel<<<BB * ECHUNK, 256>>>(x, out_sum);
}